// round 3
// baseline (speedup 1.0000x reference)
#include <cuda_runtime.h>
#include <cstdint>

#define N_NODES 100000
#define N_EDGES 1600000
#define D 128

// Scratch (no cudaMalloc allowed)
__device__ float g_h[(size_t)N_NODES * D];   // projected features, 51.2 MB
__device__ int   g_deg[N_NODES];
__device__ float g_dis[N_NODES];

// ---------------- zero init (no cudaMemsetAsync on device symbols) --------
__global__ __launch_bounds__(256) void zero_kernel(float* __restrict__ out)
{
    size_t i = (size_t)blockIdx.x * 256 + threadIdx.x;
    size_t n4 = (size_t)N_NODES * D / 4;
    if (i < n4) {
        reinterpret_cast<float4*>(out)[i] = make_float4(0.f, 0.f, 0.f, 0.f);
    }
    if (i < N_NODES) {
        g_deg[i] = 0;
    }
}

// ---------------- GEMM: h = x @ W^T + b  (M=100000, N=K=128) ----------------
__global__ __launch_bounds__(256) void gemm_kernel(
    const float* __restrict__ x, const float* __restrict__ W,
    const float* __restrict__ b)
{
    __shared__ float xs[32][36];   // [k][row], padded
    __shared__ float ws[32][132];  // [k][col], padded

    const int tid = threadIdx.x;
    const int ty  = tid >> 5;   // 0..7  -> row group (4 rows)
    const int tx  = tid & 31;   // 0..31 -> col group (4 cols)
    const int m0  = blockIdx.x * 32;   // 100000 % 32 == 0 exactly

    float acc[4][4];
#pragma unroll
    for (int i = 0; i < 4; i++)
#pragma unroll
        for (int j = 0; j < 4; j++) acc[i][j] = 0.f;

#pragma unroll
    for (int kt = 0; kt < D; kt += 32) {
#pragma unroll
        for (int s = 0; s < 4; s++) {
            int idx = tid + s * 256;
            int r = idx >> 5, kk = idx & 31;
            xs[kk][r] = x[(size_t)(m0 + r) * D + kt + kk];
        }
#pragma unroll
        for (int s = 0; s < 16; s++) {
            int idx = tid + s * 256;
            int c = idx >> 5, kk = idx & 31;
            ws[kk][c] = W[(size_t)c * D + kt + kk];
        }
        __syncthreads();
#pragma unroll
        for (int kk = 0; kk < 32; kk++) {
            float4 a  = *reinterpret_cast<const float4*>(&xs[kk][ty * 4]);
            float4 bb = *reinterpret_cast<const float4*>(&ws[kk][tx * 4]);
            float av[4] = {a.x, a.y, a.z, a.w};
            float bv[4] = {bb.x, bb.y, bb.z, bb.w};
#pragma unroll
            for (int i = 0; i < 4; i++)
#pragma unroll
                for (int j = 0; j < 4; j++) acc[i][j] += av[i] * bv[j];
        }
        __syncthreads();
    }

    float4 bias = *reinterpret_cast<const float4*>(&b[tx * 4]);
#pragma unroll
    for (int i = 0; i < 4; i++) {
        int row = m0 + ty * 4 + i;
        float4 v;
        v.x = acc[i][0] + bias.x;
        v.y = acc[i][1] + bias.y;
        v.z = acc[i][2] + bias.z;
        v.w = acc[i][3] + bias.w;
        *reinterpret_cast<float4*>(&g_h[(size_t)row * D + tx * 4]) = v;
    }
}

// ---------------- degree count over src (edge_index is int32!) -------------
__global__ __launch_bounds__(256) void deg_kernel(const int* __restrict__ ei)
{
    int e = blockIdx.x * 256 + threadIdx.x;
    if (e < N_EDGES) {
        atomicAdd(&g_deg[ei[e]], 1);
    }
}

// ---------------- dis = rsqrt(deg + 1 self loop) ----------------
__global__ __launch_bounds__(256) void dis_kernel()
{
    int i = blockIdx.x * 256 + threadIdx.x;
    if (i < N_NODES) {
        g_dis[i] = rsqrtf((float)(g_deg[i] + 1));
    }
}

// ---------------- scatter: warp per edge, vector red into d_out ------------
__global__ __launch_bounds__(256) void scatter_kernel(
    const int* __restrict__ ei, float* __restrict__ agg)
{
    const int warp = (blockIdx.x * 256 + threadIdx.x) >> 5;  // edge id
    const int lane = threadIdx.x & 31;
    if (warp >= N_EDGES) return;

    const int src = ei[warp];
    const int dst = ei[N_EDGES + warp];
    const float norm = g_dis[src] * g_dis[dst];

    float4 hv = *reinterpret_cast<const float4*>(&g_h[(size_t)src * D + lane * 4]);
    float vx = norm * hv.x, vy = norm * hv.y, vz = norm * hv.z, vw = norm * hv.w;

    float* p = agg + (size_t)dst * D + lane * 4;
    asm volatile("red.global.add.v4.f32 [%0], {%1, %2, %3, %4};"
                 :: "l"(p), "f"(vx), "f"(vy), "f"(vz), "f"(vw)
                 : "memory");
}

// ---------------- epilogue: add self-loop msg, relu, scale ----------------
__global__ __launch_bounds__(256) void final_kernel(float* __restrict__ out)
{
    const float coef = 0.125f;  // sqrt(2/128)
    int gid = blockIdx.x * 256 + threadIdx.x;         // N_NODES*32 threads
    int row = gid >> 5;
    int lane = gid & 31;
    if (row >= N_NODES) return;
    float s = g_dis[row];
    float sn = s * s;  // self-loop norm dis[i]*dis[i]

    float4 a  = *reinterpret_cast<const float4*>(&out[(size_t)row * D + lane * 4]);
    float4 h4 = *reinterpret_cast<const float4*>(&g_h[(size_t)row * D + lane * 4]);
    float4 v;
    v.x = coef * fmaxf(a.x + sn * h4.x, 0.f);
    v.y = coef * fmaxf(a.y + sn * h4.y, 0.f);
    v.z = coef * fmaxf(a.z + sn * h4.z, 0.f);
    v.w = coef * fmaxf(a.w + sn * h4.w, 0.f);
    *reinterpret_cast<float4*>(&out[(size_t)row * D + lane * 4]) = v;
}

extern "C" void kernel_launch(void* const* d_in, const int* in_sizes, int n_in,
                              void* d_out, int out_size)
{
    const float* x  = (const float*)d_in[0];
    const int*   ei = (const int*)d_in[1];   // int32: JAX x64 disabled
    const float* W  = (const float*)d_in[2];
    const float* b  = (const float*)d_in[3];
    float* out = (float*)d_out;

    // 1. zero degree counters + output accumulator (kernel, not memset)
    {
        size_t n4 = (size_t)N_NODES * D / 4;   // 3,200,000
        zero_kernel<<<(int)((n4 + 255) / 256), 256>>>(out);
    }

    // 2. projection h = xW^T + b
    gemm_kernel<<<N_NODES / 32, 256>>>(x, W, b);

    // 3. degrees + inverse sqrt
    deg_kernel<<<(N_EDGES + 255) / 256, 256>>>(ei);
    dis_kernel<<<(N_NODES + 255) / 256, 256>>>();

    // 4. edge scatter (warp per edge)
    scatter_kernel<<<(N_EDGES * 32) / 256, 256>>>(ei, out);

    // 5. self-loop + relu + scale
    final_kernel<<<(N_NODES * 32 + 255) / 256, 256>>>(out);
}

// round 4
// speedup vs baseline: 1.2650x; 1.2650x over previous
#include <cuda_runtime.h>
#include <cstdint>

#define N_NODES 100000
#define N_EDGES 1600000
#define D 128
#define N_PAD 102400   // 1024*100, padded so the scan needs no guards

// Scratch (no cudaMalloc allowed)
__device__ float g_h[(size_t)N_NODES * D];   // projected features, 51.2 MB
__device__ int   g_deg[N_NODES];             // out-degree over src (for norm)
__device__ float g_dis[N_NODES];             // (deg+1)^-0.5
__device__ int   g_cnt[N_PAD];               // in-degree over dst (for CSR)
__device__ int   g_off[N_PAD + 4];           // CSR offsets (exclusive prefix)
__device__ int   g_cursor[N_PAD];            // fill cursors
__device__ int   g_bucket[N_EDGES];          // src ids grouped by dst

// ---------------- zero counters ----------------
__global__ __launch_bounds__(256) void zero_kernel()
{
    int i = blockIdx.x * 256 + threadIdx.x;
    if (i < N_PAD) g_cnt[i] = 0;
    if (i < N_NODES) g_deg[i] = 0;
}

// ---------------- GEMM: h = x @ W^T + b  (M=100000, N=K=128) ----------------
__global__ __launch_bounds__(256) void gemm_kernel(
    const float* __restrict__ x, const float* __restrict__ W,
    const float* __restrict__ b)
{
    __shared__ float xs[32][36];   // [k][row], padded
    __shared__ float ws[32][132];  // [k][col], padded

    const int tid = threadIdx.x;
    const int ty  = tid >> 5;   // 0..7  -> row group (4 rows)
    const int tx  = tid & 31;   // 0..31 -> col group (4 cols)
    const int m0  = blockIdx.x * 32;

    float acc[4][4];
#pragma unroll
    for (int i = 0; i < 4; i++)
#pragma unroll
        for (int j = 0; j < 4; j++) acc[i][j] = 0.f;

#pragma unroll
    for (int kt = 0; kt < D; kt += 32) {
#pragma unroll
        for (int s = 0; s < 4; s++) {
            int idx = tid + s * 256;
            int r = idx >> 5, kk = idx & 31;
            xs[kk][r] = x[(size_t)(m0 + r) * D + kt + kk];
        }
#pragma unroll
        for (int s = 0; s < 16; s++) {
            int idx = tid + s * 256;
            int c = idx >> 5, kk = idx & 31;
            ws[kk][c] = W[(size_t)c * D + kt + kk];
        }
        __syncthreads();
#pragma unroll
        for (int kk = 0; kk < 32; kk++) {
            float4 a  = *reinterpret_cast<const float4*>(&xs[kk][ty * 4]);
            float4 bb = *reinterpret_cast<const float4*>(&ws[kk][tx * 4]);
            float av[4] = {a.x, a.y, a.z, a.w};
            float bv[4] = {bb.x, bb.y, bb.z, bb.w};
#pragma unroll
            for (int i = 0; i < 4; i++)
#pragma unroll
                for (int j = 0; j < 4; j++) acc[i][j] += av[i] * bv[j];
        }
        __syncthreads();
    }

    float4 bias = *reinterpret_cast<const float4*>(&b[tx * 4]);
#pragma unroll
    for (int i = 0; i < 4; i++) {
        int row = m0 + ty * 4 + i;
        float4 v;
        v.x = acc[i][0] + bias.x;
        v.y = acc[i][1] + bias.y;
        v.z = acc[i][2] + bias.z;
        v.w = acc[i][3] + bias.w;
        *reinterpret_cast<float4*>(&g_h[(size_t)row * D + tx * 4]) = v;
    }
}

// ---------------- fused histogram: deg over src, cnt over dst --------------
__global__ __launch_bounds__(256) void hist_kernel(const int* __restrict__ ei)
{
    int e = blockIdx.x * 256 + threadIdx.x;
    if (e < N_EDGES) {
        atomicAdd(&g_deg[ei[e]], 1);
        atomicAdd(&g_cnt[ei[N_EDGES + e]], 1);
    }
}

// ---------------- dis = rsqrt(deg + 1 self loop) ----------------
__global__ __launch_bounds__(256) void dis_kernel()
{
    int i = blockIdx.x * 256 + threadIdx.x;
    if (i < N_NODES) {
        g_dis[i] = rsqrtf((float)(g_deg[i] + 1));
    }
}

// ---------------- single-block exclusive scan over g_cnt -------------------
// 1024 threads, 100 elems each (25 int4). Padding guarantees no bounds checks.
__global__ __launch_bounds__(1024) void scan_kernel()
{
    __shared__ int ssum[1024];
    const int tid = threadIdx.x;
    const int4* cnt4 = reinterpret_cast<const int4*>(g_cnt);

    int s = 0;
#pragma unroll
    for (int k = 0; k < 25; k++) {
        int4 v = cnt4[tid * 25 + k];
        s += v.x + v.y + v.z + v.w;
    }
    ssum[tid] = s;
    __syncthreads();

    // Hillis-Steele inclusive scan
    for (int d = 1; d < 1024; d <<= 1) {
        int v = (tid >= d) ? ssum[tid - d] : 0;
        __syncthreads();
        ssum[tid] += v;
        __syncthreads();
    }
    int running = (tid == 0) ? 0 : ssum[tid - 1];   // exclusive prefix

    int4* off4 = reinterpret_cast<int4*>(g_off);
    int4* cur4 = reinterpret_cast<int4*>(g_cursor);
#pragma unroll
    for (int k = 0; k < 25; k++) {
        int4 c = cnt4[tid * 25 + k];
        int4 o;
        o.x = running;              running += c.x;
        o.y = running;              running += c.y;
        o.z = running;              running += c.z;
        o.w = running;              running += c.w;
        off4[tid * 25 + k] = o;
        cur4[tid * 25 + k] = o;
    }
    // g_off[100000] is written by the thread owning that index (tid=1000,k=0),
    // padding counts are zero so it equals N_EDGES. Nothing extra needed.
}

// ---------------- bucket fill: group src ids by dst -------------------------
__global__ __launch_bounds__(256) void fill_kernel(const int* __restrict__ ei)
{
    int e = blockIdx.x * 256 + threadIdx.x;
    if (e < N_EDGES) {
        int src = ei[e];
        int dst = ei[N_EDGES + e];
        int pos = atomicAdd(&g_cursor[dst], 1);
        g_bucket[pos] = src;
    }
}

// ---------------- gather: warp per node, fused epilogue --------------------
__global__ __launch_bounds__(256) void gather_kernel(float* __restrict__ out)
{
    const int node = blockIdx.x * 8 + (threadIdx.x >> 5);
    const int lane = threadIdx.x & 31;
    if (node >= N_NODES) return;

    const int start = g_off[node];
    const int end   = g_off[node + 1];
    const float dd  = g_dis[node];

    // self-loop message: dis[i]^2 * h[i]
    float4 acc;
    {
        float4 hs = *reinterpret_cast<const float4*>(&g_h[(size_t)node * D + lane * 4]);
        float sn = dd * dd;
        acc.x = sn * hs.x; acc.y = sn * hs.y; acc.z = sn * hs.z; acc.w = sn * hs.w;
    }

    int j = start;
    // 2-way unrolled to expose MLP on the random h-row gathers
    for (; j + 1 < end; j += 2) {
        int s0 = g_bucket[j];
        int s1 = g_bucket[j + 1];
        float n0 = dd * g_dis[s0];
        float n1 = dd * g_dis[s1];
        float4 h0 = *reinterpret_cast<const float4*>(&g_h[(size_t)s0 * D + lane * 4]);
        float4 h1 = *reinterpret_cast<const float4*>(&g_h[(size_t)s1 * D + lane * 4]);
        acc.x += n0 * h0.x; acc.y += n0 * h0.y; acc.z += n0 * h0.z; acc.w += n0 * h0.w;
        acc.x += n1 * h1.x; acc.y += n1 * h1.y; acc.z += n1 * h1.z; acc.w += n1 * h1.w;
    }
    if (j < end) {
        int s0 = g_bucket[j];
        float n0 = dd * g_dis[s0];
        float4 h0 = *reinterpret_cast<const float4*>(&g_h[(size_t)s0 * D + lane * 4]);
        acc.x += n0 * h0.x; acc.y += n0 * h0.y; acc.z += n0 * h0.z; acc.w += n0 * h0.w;
    }

    const float coef = 0.125f;  // sqrt(2/128)
    float4 v;
    v.x = coef * fmaxf(acc.x, 0.f);
    v.y = coef * fmaxf(acc.y, 0.f);
    v.z = coef * fmaxf(acc.z, 0.f);
    v.w = coef * fmaxf(acc.w, 0.f);
    *reinterpret_cast<float4*>(&out[(size_t)node * D + lane * 4]) = v;
}

extern "C" void kernel_launch(void* const* d_in, const int* in_sizes, int n_in,
                              void* d_out, int out_size)
{
    const float* x  = (const float*)d_in[0];
    const int*   ei = (const int*)d_in[1];   // int32: JAX x64 disabled
    const float* W  = (const float*)d_in[2];
    const float* b  = (const float*)d_in[3];
    float* out = (float*)d_out;

    zero_kernel<<<(N_PAD + 255) / 256, 256>>>();
    gemm_kernel<<<N_NODES / 32, 256>>>(x, W, b);
    hist_kernel<<<(N_EDGES + 255) / 256, 256>>>(ei);
    dis_kernel<<<(N_NODES + 255) / 256, 256>>>();
    scan_kernel<<<1, 1024>>>();
    fill_kernel<<<(N_EDGES + 255) / 256, 256>>>(ei);
    gather_kernel<<<(N_NODES + 7) / 8, 256>>>(out);
}

// round 5
// speedup vs baseline: 1.3185x; 1.0423x over previous
#include <cuda_runtime.h>
#include <cstdint>

#define N_NODES 100000
#define N_EDGES 1600000
#define D 128
#define N_PAD 102400   // 1024*100, padded so the scan needs no guards

// Scratch (no cudaMalloc allowed)
__device__ float g_h[(size_t)N_NODES * D];   // dis-premultiplied projected feats
__device__ int   g_deg[N_NODES];             // out-degree over src (for norm)
__device__ float g_dis[N_NODES];             // (deg+1)^-0.5
__device__ int   g_cnt[N_PAD];               // in-degree over dst (for CSR)
__device__ int   g_off[N_PAD + 4];           // CSR offsets (exclusive prefix)
__device__ int   g_cursor[N_PAD];            // fill cursors
__device__ int   g_bucket[N_EDGES];          // src ids grouped by dst

// ---------------- f32x2 packed-math helpers ----------------
__device__ __forceinline__ unsigned long long dup2(float v) {
    unsigned long long r;
    asm("mov.b64 %0, {%1, %1};" : "=l"(r) : "f"(v));
    return r;
}
__device__ __forceinline__ unsigned long long fma2(
    unsigned long long a, unsigned long long b, unsigned long long c) {
    unsigned long long d;
    asm("fma.rn.f32x2 %0, %1, %2, %3;" : "=l"(d) : "l"(a), "l"(b), "l"(c));
    return d;
}

// ---------------- zero counters ----------------
__global__ __launch_bounds__(256) void zero_kernel()
{
    int i = blockIdx.x * 256 + threadIdx.x;
    if (i < N_PAD) g_cnt[i] = 0;
    if (i < N_NODES) g_deg[i] = 0;
}

// ---------------- fused histogram: deg over src, cnt over dst --------------
__global__ __launch_bounds__(256) void hist_kernel(const int* __restrict__ ei)
{
    int e = blockIdx.x * 256 + threadIdx.x;
    if (e < N_EDGES) {
        atomicAdd(&g_deg[ei[e]], 1);
        atomicAdd(&g_cnt[ei[N_EDGES + e]], 1);
    }
}

// ---------------- dis = rsqrt(deg + 1 self loop) ----------------
__global__ __launch_bounds__(256) void dis_kernel()
{
    int i = blockIdx.x * 256 + threadIdx.x;
    if (i < N_NODES) {
        g_dis[i] = rsqrtf((float)(g_deg[i] + 1));
    }
}

// ---------------- GEMM: h' = dis ⊙ (x @ W^T + b) ---------------------------
// 64 rows x 128 cols per block, 256 threads, 4 rows x 8 cols per thread,
// packed f32x2 accumulation.
__global__ __launch_bounds__(256) void gemm_kernel(
    const float* __restrict__ x, const float* __restrict__ W,
    const float* __restrict__ b)
{
    __shared__ float xs[32][68];    // [k][row], 272B stride (16B aligned)
    __shared__ float ws[32][132];   // [k][col], 528B stride (16B aligned)

    const int tid = threadIdx.x;
    const int rg  = tid >> 4;    // 0..15 -> rows rg*4..rg*4+3
    const int cg  = tid & 15;    // 0..15 -> cols cg*8..cg*8+7
    const int m0  = blockIdx.x * 64;

    unsigned long long acc[4][4];   // [row][colpair], bits 0 == (0.f,0.f)
#pragma unroll
    for (int i = 0; i < 4; i++)
#pragma unroll
        for (int j = 0; j < 4; j++) acc[i][j] = 0ull;

#pragma unroll
    for (int kt = 0; kt < D; kt += 32) {
        // load x tile [64 rows][32 k] -> xs[k][row]
#pragma unroll
        for (int s = 0; s < 2; s++) {
            int f = tid + s * 256;          // 0..511
            int row = f >> 3, kq = f & 7;
            int grow = m0 + row;
            if (grow >= N_NODES) grow = N_NODES - 1;
            float4 v = *reinterpret_cast<const float4*>(&x[(size_t)grow * D + kt + kq * 4]);
            xs[kq * 4 + 0][row] = v.x;
            xs[kq * 4 + 1][row] = v.y;
            xs[kq * 4 + 2][row] = v.z;
            xs[kq * 4 + 3][row] = v.w;
        }
        // load W tile [128 cols][32 k] -> ws[k][col]
#pragma unroll
        for (int s = 0; s < 4; s++) {
            int f = tid + s * 256;          // 0..1023
            int c = f >> 3, kq = f & 7;
            float4 v = *reinterpret_cast<const float4*>(&W[(size_t)c * D + kt + kq * 4]);
            ws[kq * 4 + 0][c] = v.x;
            ws[kq * 4 + 1][c] = v.y;
            ws[kq * 4 + 2][c] = v.z;
            ws[kq * 4 + 3][c] = v.w;
        }
        __syncthreads();

#pragma unroll
        for (int kk = 0; kk < 32; kk++) {
            float4 a = *reinterpret_cast<const float4*>(&xs[kk][rg * 4]);
            ulonglong2 b0 = *reinterpret_cast<const ulonglong2*>(&ws[kk][cg * 8]);
            ulonglong2 b1 = *reinterpret_cast<const ulonglong2*>(&ws[kk][cg * 8 + 4]);
            unsigned long long av[4] = {dup2(a.x), dup2(a.y), dup2(a.z), dup2(a.w)};
            unsigned long long bv[4] = {b0.x, b0.y, b1.x, b1.y};
#pragma unroll
            for (int i = 0; i < 4; i++)
#pragma unroll
                for (int j = 0; j < 4; j++)
                    acc[i][j] = fma2(av[i], bv[j], acc[i][j]);
        }
        __syncthreads();
    }

    // epilogue: h' = dis[row] * (acc + bias)
    float4 bias0 = *reinterpret_cast<const float4*>(&b[cg * 8]);
    float4 bias1 = *reinterpret_cast<const float4*>(&b[cg * 8 + 4]);
#pragma unroll
    for (int i = 0; i < 4; i++) {
        int grow = m0 + rg * 4 + i;
        if (grow >= N_NODES) break;
        float dd = g_dis[grow];
        float2 p0 = *reinterpret_cast<float2*>(&acc[i][0]);
        float2 p1 = *reinterpret_cast<float2*>(&acc[i][1]);
        float2 p2 = *reinterpret_cast<float2*>(&acc[i][2]);
        float2 p3 = *reinterpret_cast<float2*>(&acc[i][3]);
        float4 v0, v1;
        v0.x = dd * (p0.x + bias0.x);
        v0.y = dd * (p0.y + bias0.y);
        v0.z = dd * (p1.x + bias0.z);
        v0.w = dd * (p1.y + bias0.w);
        v1.x = dd * (p2.x + bias1.x);
        v1.y = dd * (p2.y + bias1.y);
        v1.z = dd * (p3.x + bias1.z);
        v1.w = dd * (p3.y + bias1.w);
        *reinterpret_cast<float4*>(&g_h[(size_t)grow * D + cg * 8])     = v0;
        *reinterpret_cast<float4*>(&g_h[(size_t)grow * D + cg * 8 + 4]) = v1;
    }
}

// ---------------- single-block exclusive scan over g_cnt -------------------
__global__ __launch_bounds__(1024) void scan_kernel()
{
    __shared__ int ssum[1024];
    const int tid = threadIdx.x;
    const int4* cnt4 = reinterpret_cast<const int4*>(g_cnt);

    int s = 0;
#pragma unroll
    for (int k = 0; k < 25; k++) {
        int4 v = cnt4[tid * 25 + k];
        s += v.x + v.y + v.z + v.w;
    }
    ssum[tid] = s;
    __syncthreads();

    for (int d = 1; d < 1024; d <<= 1) {
        int v = (tid >= d) ? ssum[tid - d] : 0;
        __syncthreads();
        ssum[tid] += v;
        __syncthreads();
    }
    int running = (tid == 0) ? 0 : ssum[tid - 1];   // exclusive prefix

    int4* off4 = reinterpret_cast<int4*>(g_off);
    int4* cur4 = reinterpret_cast<int4*>(g_cursor);
#pragma unroll
    for (int k = 0; k < 25; k++) {
        int4 c = cnt4[tid * 25 + k];
        int4 o;
        o.x = running;              running += c.x;
        o.y = running;              running += c.y;
        o.z = running;              running += c.z;
        o.w = running;              running += c.w;
        off4[tid * 25 + k] = o;
        cur4[tid * 25 + k] = o;
    }
}

// ---------------- bucket fill: group src ids by dst -------------------------
__global__ __launch_bounds__(256) void fill_kernel(const int* __restrict__ ei)
{
    int e = blockIdx.x * 256 + threadIdx.x;
    if (e < N_EDGES) {
        int src = ei[e];
        int dst = ei[N_EDGES + e];
        int pos = atomicAdd(&g_cursor[dst], 1);
        g_bucket[pos] = src;
    }
}

// ---------------- gather: warp per node, fused epilogue --------------------
// h' is dis-premultiplied, so no per-edge dis lookup:
// out[i] = coef * relu( dis[i] * (h'[i] + Σ h'[src]) )
__global__ __launch_bounds__(256) void gather_kernel(float* __restrict__ out)
{
    const int node = blockIdx.x * 8 + (threadIdx.x >> 5);
    const int lane = threadIdx.x & 31;
    if (node >= N_NODES) return;

    const int start = g_off[node];
    const int end   = g_off[node + 1];
    const float dd  = g_dis[node];

    // self-loop message: h'[node]
    float4 acc = *reinterpret_cast<const float4*>(&g_h[(size_t)node * D + lane * 4]);

    int j = start;
    for (; j + 3 < end; j += 4) {
        int s0 = g_bucket[j];
        int s1 = g_bucket[j + 1];
        int s2 = g_bucket[j + 2];
        int s3 = g_bucket[j + 3];
        float4 h0 = *reinterpret_cast<const float4*>(&g_h[(size_t)s0 * D + lane * 4]);
        float4 h1 = *reinterpret_cast<const float4*>(&g_h[(size_t)s1 * D + lane * 4]);
        float4 h2 = *reinterpret_cast<const float4*>(&g_h[(size_t)s2 * D + lane * 4]);
        float4 h3 = *reinterpret_cast<const float4*>(&g_h[(size_t)s3 * D + lane * 4]);
        acc.x += h0.x + h1.x + h2.x + h3.x;
        acc.y += h0.y + h1.y + h2.y + h3.y;
        acc.z += h0.z + h1.z + h2.z + h3.z;
        acc.w += h0.w + h1.w + h2.w + h3.w;
    }
    for (; j < end; j++) {
        int s0 = g_bucket[j];
        float4 h0 = *reinterpret_cast<const float4*>(&g_h[(size_t)s0 * D + lane * 4]);
        acc.x += h0.x; acc.y += h0.y; acc.z += h0.z; acc.w += h0.w;
    }

    const float coef = 0.125f;  // sqrt(2/128)
    float4 v;
    v.x = coef * fmaxf(dd * acc.x, 0.f);
    v.y = coef * fmaxf(dd * acc.y, 0.f);
    v.z = coef * fmaxf(dd * acc.z, 0.f);
    v.w = coef * fmaxf(dd * acc.w, 0.f);
    *reinterpret_cast<float4*>(&out[(size_t)node * D + lane * 4]) = v;
}

extern "C" void kernel_launch(void* const* d_in, const int* in_sizes, int n_in,
                              void* d_out, int out_size)
{
    const float* x  = (const float*)d_in[0];
    const int*   ei = (const int*)d_in[1];   // int32: JAX x64 disabled
    const float* W  = (const float*)d_in[2];
    const float* b  = (const float*)d_in[3];
    float* out = (float*)d_out;

    zero_kernel<<<(N_PAD + 255) / 256, 256>>>();
    hist_kernel<<<(N_EDGES + 255) / 256, 256>>>(ei);
    dis_kernel<<<(N_NODES + 255) / 256, 256>>>();
    gemm_kernel<<<(N_NODES + 63) / 64, 256>>>(x, W, b);   // needs g_dis
    scan_kernel<<<1, 1024>>>();
    fill_kernel<<<(N_EDGES + 255) / 256, 256>>>(ei);
    gather_kernel<<<(N_NODES + 7) / 8, 256>>>(out);
}

// round 6
// speedup vs baseline: 1.5892x; 1.2053x over previous
#include <cuda_runtime.h>
#include <cuda_fp16.h>
#include <cstdint>

#define N_NODES 100000
#define N_EDGES 1600000
#define D 128
#define N_PAD 102400   // 1024*100, padded so the scan needs no guards

// Scratch (no cudaMalloc allowed)
__device__ __half2 g_h[(size_t)N_NODES * (D / 2)];  // dis-premultiplied feats, fp16, 25.6 MB
__device__ int   g_deg[N_NODES];
__device__ float g_dis[N_NODES];
__device__ int   g_cnt[N_PAD];
__device__ int   g_off[N_PAD + 4];
__device__ int   g_cursor[N_PAD];
__device__ int   g_bucket[N_EDGES];

// ---------------- f32x2 packed-math helpers ----------------
__device__ __forceinline__ unsigned long long dup2(float v) {
    unsigned long long r;
    asm("mov.b64 %0, {%1, %1};" : "=l"(r) : "f"(v));
    return r;
}
__device__ __forceinline__ unsigned long long fma2(
    unsigned long long a, unsigned long long b, unsigned long long c) {
    unsigned long long d;
    asm("fma.rn.f32x2 %0, %1, %2, %3;" : "=l"(d) : "l"(a), "l"(b), "l"(c));
    return d;
}

// ---------------- zero counters ----------------
__global__ __launch_bounds__(256) void zero_kernel()
{
    int i = blockIdx.x * 256 + threadIdx.x;
    if (i < N_PAD) g_cnt[i] = 0;
    if (i < N_NODES) g_deg[i] = 0;
}

// ---------------- fused histogram: deg over src, cnt over dst --------------
__global__ __launch_bounds__(256) void hist_kernel(const int* __restrict__ ei)
{
    int e = blockIdx.x * 256 + threadIdx.x;
    if (e < N_EDGES) {
        atomicAdd(&g_deg[ei[e]], 1);
        atomicAdd(&g_cnt[ei[N_EDGES + e]], 1);
    }
}

// ---------------- dis = rsqrt(deg + 1 self loop) ----------------
__global__ __launch_bounds__(256) void dis_kernel()
{
    int i = blockIdx.x * 256 + threadIdx.x;
    if (i < N_NODES) {
        g_dis[i] = rsqrtf((float)(g_deg[i] + 1));
    }
}

// ---------------- GEMM: h' = fp16( dis ⊙ (x @ W^T + b) ) -------------------
// 128 rows x 128 cols per block, 256 threads, 8x8 per thread, f32x2 FMA.
__global__ __launch_bounds__(256) void gemm_kernel(
    const float* __restrict__ x, const float* __restrict__ W,
    const float* __restrict__ b)
{
    __shared__ float xs[32][132];   // [k][row], 528B row stride (16B aligned)
    __shared__ float ws[32][132];   // [k][col]

    const int tid = threadIdx.x;
    const int rg  = tid >> 4;    // 0..15 -> rows rg*8..rg*8+7
    const int cg  = tid & 15;    // 0..15 -> cols cg*8..cg*8+7
    const int m0  = blockIdx.x * 128;

    unsigned long long acc[8][4];   // [row][colpair]
#pragma unroll
    for (int i = 0; i < 8; i++)
#pragma unroll
        for (int j = 0; j < 4; j++) acc[i][j] = 0ull;

#pragma unroll
    for (int kt = 0; kt < D; kt += 32) {
        // x tile: 128 rows x 32 k -> xs[k][row]  (1024 float4, 4 per thread)
#pragma unroll
        for (int s = 0; s < 4; s++) {
            int f = tid + s * 256;
            int row = f >> 3, kq = f & 7;
            int grow = m0 + row;
            if (grow >= N_NODES) grow = N_NODES - 1;
            float4 v = *reinterpret_cast<const float4*>(&x[(size_t)grow * D + kt + kq * 4]);
            xs[kq * 4 + 0][row] = v.x;
            xs[kq * 4 + 1][row] = v.y;
            xs[kq * 4 + 2][row] = v.z;
            xs[kq * 4 + 3][row] = v.w;
        }
        // W tile: 128 cols x 32 k -> ws[k][col]
#pragma unroll
        for (int s = 0; s < 4; s++) {
            int f = tid + s * 256;
            int c = f >> 3, kq = f & 7;
            float4 v = *reinterpret_cast<const float4*>(&W[(size_t)c * D + kt + kq * 4]);
            ws[kq * 4 + 0][c] = v.x;
            ws[kq * 4 + 1][c] = v.y;
            ws[kq * 4 + 2][c] = v.z;
            ws[kq * 4 + 3][c] = v.w;
        }
        __syncthreads();

#pragma unroll
        for (int kk = 0; kk < 32; kk++) {
            float4 a0 = *reinterpret_cast<const float4*>(&xs[kk][rg * 8]);
            float4 a1 = *reinterpret_cast<const float4*>(&xs[kk][rg * 8 + 4]);
            ulonglong2 b0 = *reinterpret_cast<const ulonglong2*>(&ws[kk][cg * 8]);
            ulonglong2 b1 = *reinterpret_cast<const ulonglong2*>(&ws[kk][cg * 8 + 4]);
            unsigned long long av[8] = {dup2(a0.x), dup2(a0.y), dup2(a0.z), dup2(a0.w),
                                        dup2(a1.x), dup2(a1.y), dup2(a1.z), dup2(a1.w)};
            unsigned long long bv[4] = {b0.x, b0.y, b1.x, b1.y};
#pragma unroll
            for (int i = 0; i < 8; i++)
#pragma unroll
                for (int j = 0; j < 4; j++)
                    acc[i][j] = fma2(av[i], bv[j], acc[i][j]);
        }
        __syncthreads();
    }

    // epilogue: h' = half( dis[row] * (acc + bias) ), 16B store per row
    float4 bias0 = *reinterpret_cast<const float4*>(&b[cg * 8]);
    float4 bias1 = *reinterpret_cast<const float4*>(&b[cg * 8 + 4]);
    uint4* hout = reinterpret_cast<uint4*>(g_h);   // row = 16 uint4
#pragma unroll
    for (int i = 0; i < 8; i++) {
        int grow = m0 + rg * 8 + i;
        if (grow >= N_NODES) break;
        float dd = g_dis[grow];
        float2 p0 = *reinterpret_cast<float2*>(&acc[i][0]);
        float2 p1 = *reinterpret_cast<float2*>(&acc[i][1]);
        float2 p2 = *reinterpret_cast<float2*>(&acc[i][2]);
        float2 p3 = *reinterpret_cast<float2*>(&acc[i][3]);
        float2 f0 = make_float2(dd * (p0.x + bias0.x), dd * (p0.y + bias0.y));
        float2 f1 = make_float2(dd * (p1.x + bias0.z), dd * (p1.y + bias0.w));
        float2 f2 = make_float2(dd * (p2.x + bias1.x), dd * (p2.y + bias1.y));
        float2 f3 = make_float2(dd * (p3.x + bias1.z), dd * (p3.y + bias1.w));
        __half2 h0 = __float22half2_rn(f0);
        __half2 h1 = __float22half2_rn(f1);
        __half2 h2 = __float22half2_rn(f2);
        __half2 h3 = __float22half2_rn(f3);
        uint4 u;
        u.x = *reinterpret_cast<unsigned*>(&h0);
        u.y = *reinterpret_cast<unsigned*>(&h1);
        u.z = *reinterpret_cast<unsigned*>(&h2);
        u.w = *reinterpret_cast<unsigned*>(&h3);
        hout[(size_t)grow * 16 + cg] = u;
    }
}

// ---------------- single-block exclusive scan over g_cnt -------------------
__global__ __launch_bounds__(1024) void scan_kernel()
{
    __shared__ int ssum[1024];
    const int tid = threadIdx.x;
    const int4* cnt4 = reinterpret_cast<const int4*>(g_cnt);

    int s = 0;
#pragma unroll
    for (int k = 0; k < 25; k++) {
        int4 v = cnt4[tid * 25 + k];
        s += v.x + v.y + v.z + v.w;
    }
    ssum[tid] = s;
    __syncthreads();

    for (int d = 1; d < 1024; d <<= 1) {
        int v = (tid >= d) ? ssum[tid - d] : 0;
        __syncthreads();
        ssum[tid] += v;
        __syncthreads();
    }
    int running = (tid == 0) ? 0 : ssum[tid - 1];

    int4* off4 = reinterpret_cast<int4*>(g_off);
    int4* cur4 = reinterpret_cast<int4*>(g_cursor);
#pragma unroll
    for (int k = 0; k < 25; k++) {
        int4 c = cnt4[tid * 25 + k];
        int4 o;
        o.x = running;              running += c.x;
        o.y = running;              running += c.y;
        o.z = running;              running += c.z;
        o.w = running;              running += c.w;
        off4[tid * 25 + k] = o;
        cur4[tid * 25 + k] = o;
    }
}

// ---------------- bucket fill: group src ids by dst -------------------------
__global__ __launch_bounds__(256) void fill_kernel(const int* __restrict__ ei)
{
    int e = blockIdx.x * 256 + threadIdx.x;
    if (e < N_EDGES) {
        int src = ei[e];
        int dst = ei[N_EDGES + e];
        int pos = atomicAdd(&g_cursor[dst], 1);
        g_bucket[pos] = src;
    }
}

// ---------------- gather: warp per node, 2 edges/iter, fp16 rows ------------
// out[i] = coef * relu( dis[i] * (h'[i] + sum h'[src]) )
__global__ __launch_bounds__(256) void gather_kernel(float* __restrict__ out)
{
    const int node = blockIdx.x * 8 + (threadIdx.x >> 5);
    if (node >= N_NODES) return;
    const int lane = threadIdx.x & 31;
    const int hf   = lane >> 4;      // 0/1 half-warp
    const int sub  = lane & 15;      // 16 lanes cover a 256B row (LDG.128 each)

    const int start = g_off[node];
    const int end   = g_off[node + 1];
    const float dd  = g_dis[node];
    const uint4* hbase = reinterpret_cast<const uint4*>(g_h);

    float2 a0 = make_float2(0.f, 0.f), a1 = a0, a2 = a0, a3 = a0;

    // self-loop message counted once (half 0)
    if (hf == 0) {
        uint4 u = hbase[(size_t)node * 16 + sub];
        float2 f0 = __half22float2(*reinterpret_cast<__half2*>(&u.x));
        float2 f1 = __half22float2(*reinterpret_cast<__half2*>(&u.y));
        float2 f2 = __half22float2(*reinterpret_cast<__half2*>(&u.z));
        float2 f3 = __half22float2(*reinterpret_cast<__half2*>(&u.w));
        a0 = f0; a1 = f1; a2 = f2; a3 = f3;
    }

    int j = start + hf;
    // 2-way unroll per half-warp for MLP
    for (; j + 2 < end; j += 4) {
        int s0 = g_bucket[j];
        int s1 = g_bucket[j + 2];
        uint4 u0 = hbase[(size_t)s0 * 16 + sub];
        uint4 u1 = hbase[(size_t)s1 * 16 + sub];
        float2 f;
        f = __half22float2(*reinterpret_cast<__half2*>(&u0.x)); a0.x += f.x; a0.y += f.y;
        f = __half22float2(*reinterpret_cast<__half2*>(&u0.y)); a1.x += f.x; a1.y += f.y;
        f = __half22float2(*reinterpret_cast<__half2*>(&u0.z)); a2.x += f.x; a2.y += f.y;
        f = __half22float2(*reinterpret_cast<__half2*>(&u0.w)); a3.x += f.x; a3.y += f.y;
        f = __half22float2(*reinterpret_cast<__half2*>(&u1.x)); a0.x += f.x; a0.y += f.y;
        f = __half22float2(*reinterpret_cast<__half2*>(&u1.y)); a1.x += f.x; a1.y += f.y;
        f = __half22float2(*reinterpret_cast<__half2*>(&u1.z)); a2.x += f.x; a2.y += f.y;
        f = __half22float2(*reinterpret_cast<__half2*>(&u1.w)); a3.x += f.x; a3.y += f.y;
    }
    if (j < end) {
        int s0 = g_bucket[j];
        uint4 u0 = hbase[(size_t)s0 * 16 + sub];
        float2 f;
        f = __half22float2(*reinterpret_cast<__half2*>(&u0.x)); a0.x += f.x; a0.y += f.y;
        f = __half22float2(*reinterpret_cast<__half2*>(&u0.y)); a1.x += f.x; a1.y += f.y;
        f = __half22float2(*reinterpret_cast<__half2*>(&u0.z)); a2.x += f.x; a2.y += f.y;
        f = __half22float2(*reinterpret_cast<__half2*>(&u0.w)); a3.x += f.x; a3.y += f.y;
    }

    // combine the two half-warps (each lane pairs with lane^16, same features)
    a0.x += __shfl_xor_sync(0xffffffffu, a0.x, 16);
    a0.y += __shfl_xor_sync(0xffffffffu, a0.y, 16);
    a1.x += __shfl_xor_sync(0xffffffffu, a1.x, 16);
    a1.y += __shfl_xor_sync(0xffffffffu, a1.y, 16);
    a2.x += __shfl_xor_sync(0xffffffffu, a2.x, 16);
    a2.y += __shfl_xor_sync(0xffffffffu, a2.y, 16);
    a3.x += __shfl_xor_sync(0xffffffffu, a3.x, 16);
    a3.y += __shfl_xor_sync(0xffffffffu, a3.y, 16);

    const float coef = 0.125f;  // sqrt(2/128)
    // lane writes features sub*8 + hf*4 .. +3
    float4 v;
    if (hf == 0) {
        v.x = a0.x; v.y = a0.y; v.z = a1.x; v.w = a1.y;
    } else {
        v.x = a2.x; v.y = a2.y; v.z = a3.x; v.w = a3.y;
    }
    v.x = coef * fmaxf(dd * v.x, 0.f);
    v.y = coef * fmaxf(dd * v.y, 0.f);
    v.z = coef * fmaxf(dd * v.z, 0.f);
    v.w = coef * fmaxf(dd * v.w, 0.f);
    *reinterpret_cast<float4*>(&out[(size_t)node * D + sub * 8 + hf * 4]) = v;
}

extern "C" void kernel_launch(void* const* d_in, const int* in_sizes, int n_in,
                              void* d_out, int out_size)
{
    const float* x  = (const float*)d_in[0];
    const int*   ei = (const int*)d_in[1];   // int32: JAX x64 disabled
    const float* W  = (const float*)d_in[2];
    const float* b  = (const float*)d_in[3];
    float* out = (float*)d_out;

    zero_kernel<<<(N_PAD + 255) / 256, 256>>>();
    hist_kernel<<<(N_EDGES + 255) / 256, 256>>>(ei);
    dis_kernel<<<(N_NODES + 255) / 256, 256>>>();
    gemm_kernel<<<(N_NODES + 127) / 128, 256>>>(x, W, b);   // needs g_dis
    scan_kernel<<<1, 1024>>>();
    fill_kernel<<<(N_EDGES + 255) / 256, 256>>>(ei);
    gather_kernel<<<(N_NODES + 7) / 8, 256>>>(out);
}

// round 8
// speedup vs baseline: 1.6329x; 1.0275x over previous
#include <cuda_runtime.h>
#include <cuda_fp16.h>
#include <cstdint>

#define N_NODES 100000
#define N_EDGES 1600000
#define D 128
#define N_PAD 102400   // 1024*100, padded so the scan needs no guards

// Scratch (no cudaMalloc allowed)
__device__ __half2 g_h[(size_t)N_NODES * (D / 2)];  // dis-premultiplied feats, fp16
__device__ int   g_deg[N_NODES];
__device__ float g_dis[N_NODES];
__device__ int   g_cnt[N_PAD];
__device__ int   g_off[N_PAD + 4];
__device__ int   g_cursor[N_PAD];
__device__ int   g_bucket[N_EDGES];

// ---------------- f32x2 packed-math helpers ----------------
__device__ __forceinline__ unsigned long long dup2(float v) {
    unsigned long long r;
    asm("mov.b64 %0, {%1, %1};" : "=l"(r) : "f"(v));
    return r;
}
__device__ __forceinline__ unsigned long long fma2(
    unsigned long long a, unsigned long long b, unsigned long long c) {
    unsigned long long d;
    asm("fma.rn.f32x2 %0, %1, %2, %3;" : "=l"(d) : "l"(a), "l"(b), "l"(c));
    return d;
}

// ---------------- zero counters ----------------
__global__ __launch_bounds__(256) void zero_kernel()
{
    int i = blockIdx.x * 256 + threadIdx.x;
    if (i < N_PAD) g_cnt[i] = 0;
    if (i < N_NODES) g_deg[i] = 0;
}

// ---------------- fused histogram: deg over src, cnt over dst --------------
__global__ __launch_bounds__(256) void hist_kernel(const int* __restrict__ ei)
{
    int e = blockIdx.x * 256 + threadIdx.x;
    if (e < N_EDGES) {
        atomicAdd(&g_deg[ei[e]], 1);
        atomicAdd(&g_cnt[ei[N_EDGES + e]], 1);
    }
}

// ---------------- dis = rsqrt(deg + 1 self loop) ----------------
__global__ __launch_bounds__(256) void dis_kernel()
{
    int i = blockIdx.x * 256 + threadIdx.x;
    if (i < N_NODES) {
        g_dis[i] = rsqrtf((float)(g_deg[i] + 1));
    }
}

// ---------------- GEMM: h' = fp16( dis ⊙ (x @ W^T + b) ) -------------------
// 128x128 block tile, 256 threads, 8x8 per thread, f32x2 FMA, 2 CTAs/SM.
__global__ __launch_bounds__(256, 2) void gemm_kernel(
    const float* __restrict__ x, const float* __restrict__ W,
    const float* __restrict__ b)
{
    __shared__ float xs[32][132];   // [k][row]
    __shared__ float ws[32][132];   // [k][col]

    const int tid = threadIdx.x;
    const int rg  = tid >> 4;    // 0..15 -> rows rg*8..rg*8+7
    const int cg  = tid & 15;    // 0..15 -> cols cg*8..cg*8+7
    const int m0  = blockIdx.x * 128;

    unsigned long long acc[8][4];
#pragma unroll
    for (int i = 0; i < 8; i++)
#pragma unroll
        for (int j = 0; j < 4; j++) acc[i][j] = 0ull;

#pragma unroll
    for (int kt = 0; kt < D; kt += 32) {
#pragma unroll
        for (int s = 0; s < 4; s++) {
            int f = tid + s * 256;
            int row = f >> 3, kq = f & 7;
            int grow = m0 + row;
            if (grow >= N_NODES) grow = N_NODES - 1;
            float4 v = *reinterpret_cast<const float4*>(&x[(size_t)grow * D + kt + kq * 4]);
            xs[kq * 4 + 0][row] = v.x;
            xs[kq * 4 + 1][row] = v.y;
            xs[kq * 4 + 2][row] = v.z;
            xs[kq * 4 + 3][row] = v.w;
        }
#pragma unroll
        for (int s = 0; s < 4; s++) {
            int f = tid + s * 256;
            int c = f >> 3, kq = f & 7;
            float4 v = *reinterpret_cast<const float4*>(&W[(size_t)c * D + kt + kq * 4]);
            ws[kq * 4 + 0][c] = v.x;
            ws[kq * 4 + 1][c] = v.y;
            ws[kq * 4 + 2][c] = v.z;
            ws[kq * 4 + 3][c] = v.w;
        }
        __syncthreads();

#pragma unroll
        for (int kk = 0; kk < 32; kk++) {
            float4 a0 = *reinterpret_cast<const float4*>(&xs[kk][rg * 8]);
            float4 a1 = *reinterpret_cast<const float4*>(&xs[kk][rg * 8 + 4]);
            ulonglong2 b0 = *reinterpret_cast<const ulonglong2*>(&ws[kk][cg * 8]);
            ulonglong2 b1 = *reinterpret_cast<const ulonglong2*>(&ws[kk][cg * 8 + 4]);
            unsigned long long av[8] = {dup2(a0.x), dup2(a0.y), dup2(a0.z), dup2(a0.w),
                                        dup2(a1.x), dup2(a1.y), dup2(a1.z), dup2(a1.w)};
            unsigned long long bv[4] = {b0.x, b0.y, b1.x, b1.y};
#pragma unroll
            for (int i = 0; i < 8; i++)
#pragma unroll
                for (int j = 0; j < 4; j++)
                    acc[i][j] = fma2(av[i], bv[j], acc[i][j]);
        }
        __syncthreads();
    }

    float4 bias0 = *reinterpret_cast<const float4*>(&b[cg * 8]);
    float4 bias1 = *reinterpret_cast<const float4*>(&b[cg * 8 + 4]);
    uint4* hout = reinterpret_cast<uint4*>(g_h);
#pragma unroll
    for (int i = 0; i < 8; i++) {
        int grow = m0 + rg * 8 + i;
        if (grow >= N_NODES) break;
        float dd = g_dis[grow];
        float2 p0 = *reinterpret_cast<float2*>(&acc[i][0]);
        float2 p1 = *reinterpret_cast<float2*>(&acc[i][1]);
        float2 p2 = *reinterpret_cast<float2*>(&acc[i][2]);
        float2 p3 = *reinterpret_cast<float2*>(&acc[i][3]);
        __half2 h0 = __float22half2_rn(make_float2(dd * (p0.x + bias0.x), dd * (p0.y + bias0.y)));
        __half2 h1 = __float22half2_rn(make_float2(dd * (p1.x + bias0.z), dd * (p1.y + bias0.w)));
        __half2 h2 = __float22half2_rn(make_float2(dd * (p2.x + bias1.x), dd * (p2.y + bias1.y)));
        __half2 h3 = __float22half2_rn(make_float2(dd * (p3.x + bias1.z), dd * (p3.y + bias1.w)));
        uint4 u;
        u.x = *reinterpret_cast<unsigned*>(&h0);
        u.y = *reinterpret_cast<unsigned*>(&h1);
        u.z = *reinterpret_cast<unsigned*>(&h2);
        u.w = *reinterpret_cast<unsigned*>(&h3);
        hout[(size_t)grow * 16 + cg] = u;
    }
}

// ---------------- single-block exclusive scan over g_cnt -------------------
__global__ __launch_bounds__(1024) void scan_kernel()
{
    __shared__ int ssum[1024];
    const int tid = threadIdx.x;
    const int4* cnt4 = reinterpret_cast<const int4*>(g_cnt);

    int s = 0;
#pragma unroll
    for (int k = 0; k < 25; k++) {
        int4 v = cnt4[tid * 25 + k];
        s += v.x + v.y + v.z + v.w;
    }
    ssum[tid] = s;
    __syncthreads();

    for (int d = 1; d < 1024; d <<= 1) {
        int v = (tid >= d) ? ssum[tid - d] : 0;
        __syncthreads();
        ssum[tid] += v;
        __syncthreads();
    }
    int running = (tid == 0) ? 0 : ssum[tid - 1];

    int4* off4 = reinterpret_cast<int4*>(g_off);
    int4* cur4 = reinterpret_cast<int4*>(g_cursor);
#pragma unroll
    for (int k = 0; k < 25; k++) {
        int4 c = cnt4[tid * 25 + k];
        int4 o;
        o.x = running;              running += c.x;
        o.y = running;              running += c.y;
        o.z = running;              running += c.z;
        o.w = running;              running += c.w;
        off4[tid * 25 + k] = o;
        cur4[tid * 25 + k] = o;
    }
}

// ---------------- bucket fill: group src ids by dst -------------------------
__global__ __launch_bounds__(256) void fill_kernel(const int* __restrict__ ei)
{
    int e = blockIdx.x * 256 + threadIdx.x;
    if (e < N_EDGES) {
        int src = ei[e];
        int dst = ei[N_EDGES + e];
        int pos = atomicAdd(&g_cursor[dst], 1);
        g_bucket[pos] = src;
    }
}

// ---------------- gather: warp per node, shfl-distributed indices -----------
// One coalesced LDG fetches up to 32 src ids; shfl distributes them. ALL loop
// bounds are warp-uniform (depend only on m), so every __shfl_sync is executed
// by the full warp — the half-warp offset hf only selects WHICH lane to read.
__global__ __launch_bounds__(256) void gather_kernel(float* __restrict__ out)
{
    const int node = blockIdx.x * 8 + (threadIdx.x >> 5);
    if (node >= N_NODES) return;
    const int lane = threadIdx.x & 31;
    const int hf   = lane >> 4;      // 0/1 half-warp
    const int sub  = lane & 15;      // 16 lanes cover a 256B fp16 row
    const unsigned FULL = 0xffffffffu;

    const int start = g_off[node];
    const int end   = g_off[node + 1];
    const int cnt   = end - start;
    const float dd  = g_dis[node];
    const uint4* hbase = reinterpret_cast<const uint4*>(g_h);

    // coalesced index prefetch: lane L holds src id of edge L
    int idx = (lane < cnt) ? g_bucket[start + lane] : 0;

    float2 a0 = make_float2(0.f, 0.f), a1 = a0, a2 = a0, a3 = a0;

    // self-loop counted once (half 0)
    if (hf == 0) {
        uint4 u = hbase[(size_t)node * 16 + sub];
        a0 = __half22float2(*reinterpret_cast<__half2*>(&u.x));
        a1 = __half22float2(*reinterpret_cast<__half2*>(&u.y));
        a2 = __half22float2(*reinterpret_cast<__half2*>(&u.z));
        a3 = __half22float2(*reinterpret_cast<__half2*>(&u.w));
    }

    const int m = cnt < 32 ? cnt : 32;
    const int full8 = m & ~7;        // warp-uniform chunk bound

    // 8 edges per iteration (4 per half-warp, 4 loads in flight each)
    for (int base = 0; base < full8; base += 8) {
        int s0 = __shfl_sync(FULL, idx, base + hf);
        int s1 = __shfl_sync(FULL, idx, base + hf + 2);
        int s2 = __shfl_sync(FULL, idx, base + hf + 4);
        int s3 = __shfl_sync(FULL, idx, base + hf + 6);
        uint4 u0 = hbase[(size_t)s0 * 16 + sub];
        uint4 u1 = hbase[(size_t)s1 * 16 + sub];
        uint4 u2 = hbase[(size_t)s2 * 16 + sub];
        uint4 u3 = hbase[(size_t)s3 * 16 + sub];
        float2 f;
        f = __half22float2(*reinterpret_cast<__half2*>(&u0.x)); a0.x += f.x; a0.y += f.y;
        f = __half22float2(*reinterpret_cast<__half2*>(&u0.y)); a1.x += f.x; a1.y += f.y;
        f = __half22float2(*reinterpret_cast<__half2*>(&u0.z)); a2.x += f.x; a2.y += f.y;
        f = __half22float2(*reinterpret_cast<__half2*>(&u0.w)); a3.x += f.x; a3.y += f.y;
        f = __half22float2(*reinterpret_cast<__half2*>(&u1.x)); a0.x += f.x; a0.y += f.y;
        f = __half22float2(*reinterpret_cast<__half2*>(&u1.y)); a1.x += f.x; a1.y += f.y;
        f = __half22float2(*reinterpret_cast<__half2*>(&u1.z)); a2.x += f.x; a2.y += f.y;
        f = __half22float2(*reinterpret_cast<__half2*>(&u1.w)); a3.x += f.x; a3.y += f.y;
        f = __half22float2(*reinterpret_cast<__half2*>(&u2.x)); a0.x += f.x; a0.y += f.y;
        f = __half22float2(*reinterpret_cast<__half2*>(&u2.y)); a1.x += f.x; a1.y += f.y;
        f = __half22float2(*reinterpret_cast<__half2*>(&u2.z)); a2.x += f.x; a2.y += f.y;
        f = __half22float2(*reinterpret_cast<__half2*>(&u2.w)); a3.x += f.x; a3.y += f.y;
        f = __half22float2(*reinterpret_cast<__half2*>(&u3.x)); a0.x += f.x; a0.y += f.y;
        f = __half22float2(*reinterpret_cast<__half2*>(&u3.y)); a1.x += f.x; a1.y += f.y;
        f = __half22float2(*reinterpret_cast<__half2*>(&u3.z)); a2.x += f.x; a2.y += f.y;
        f = __half22float2(*reinterpret_cast<__half2*>(&u3.w)); a3.x += f.x; a3.y += f.y;
    }
    // remainder: uniform loop, shfl unconditional (clamped), load predicated
    for (int r = full8; r < m; r += 2) {
        int ee = r + hf;
        int s0 = __shfl_sync(FULL, idx, ee & 31);
        if (ee < m) {
            uint4 u0 = hbase[(size_t)s0 * 16 + sub];
            float2 f;
            f = __half22float2(*reinterpret_cast<__half2*>(&u0.x)); a0.x += f.x; a0.y += f.y;
            f = __half22float2(*reinterpret_cast<__half2*>(&u0.y)); a1.x += f.x; a1.y += f.y;
            f = __half22float2(*reinterpret_cast<__half2*>(&u0.z)); a2.x += f.x; a2.y += f.y;
            f = __half22float2(*reinterpret_cast<__half2*>(&u0.w)); a3.x += f.x; a3.y += f.y;
        }
    }
    // rare tail: degree > 32 (no warp collectives inside — divergence OK)
    for (int j = start + 32 + hf; j < end; j += 2) {
        int s0 = g_bucket[j];
        uint4 u0 = hbase[(size_t)s0 * 16 + sub];
        float2 f;
        f = __half22float2(*reinterpret_cast<__half2*>(&u0.x)); a0.x += f.x; a0.y += f.y;
        f = __half22float2(*reinterpret_cast<__half2*>(&u0.y)); a1.x += f.x; a1.y += f.y;
        f = __half22float2(*reinterpret_cast<__half2*>(&u0.z)); a2.x += f.x; a2.y += f.y;
        f = __half22float2(*reinterpret_cast<__half2*>(&u0.w)); a3.x += f.x; a3.y += f.y;
    }

    // combine the two half-warps (lane pairs with lane^16, same features)
    a0.x += __shfl_xor_sync(FULL, a0.x, 16);
    a0.y += __shfl_xor_sync(FULL, a0.y, 16);
    a1.x += __shfl_xor_sync(FULL, a1.x, 16);
    a1.y += __shfl_xor_sync(FULL, a1.y, 16);
    a2.x += __shfl_xor_sync(FULL, a2.x, 16);
    a2.y += __shfl_xor_sync(FULL, a2.y, 16);
    a3.x += __shfl_xor_sync(FULL, a3.x, 16);
    a3.y += __shfl_xor_sync(FULL, a3.y, 16);

    const float coef = 0.125f;  // sqrt(2/128)
    float4 v;
    if (hf == 0) {
        v.x = a0.x; v.y = a0.y; v.z = a1.x; v.w = a1.y;
    } else {
        v.x = a2.x; v.y = a2.y; v.z = a3.x; v.w = a3.y;
    }
    v.x = coef * fmaxf(dd * v.x, 0.f);
    v.y = coef * fmaxf(dd * v.y, 0.f);
    v.z = coef * fmaxf(dd * v.z, 0.f);
    v.w = coef * fmaxf(dd * v.w, 0.f);
    *reinterpret_cast<float4*>(&out[(size_t)node * D + sub * 8 + hf * 4]) = v;
}

extern "C" void kernel_launch(void* const* d_in, const int* in_sizes, int n_in,
                              void* d_out, int out_size)
{
    const float* x  = (const float*)d_in[0];
    const int*   ei = (const int*)d_in[1];   // int32: JAX x64 disabled
    const float* W  = (const float*)d_in[2];
    const float* b  = (const float*)d_in[3];
    float* out = (float*)d_out;

    zero_kernel<<<(N_PAD + 255) / 256, 256>>>();
    hist_kernel<<<(N_EDGES + 255) / 256, 256>>>(ei);
    dis_kernel<<<(N_NODES + 255) / 256, 256>>>();
    gemm_kernel<<<(N_NODES + 127) / 128, 256>>>(x, W, b);   // needs g_dis
    scan_kernel<<<1, 1024>>>();
    fill_kernel<<<(N_EDGES + 255) / 256, 256>>>(ei);
    gather_kernel<<<(N_NODES + 7) / 8, 256>>>(out);
}

// round 9
// speedup vs baseline: 2.0189x; 1.2364x over previous
#include <cuda_runtime.h>
#include <cuda_fp16.h>
#include <cstdint>

#define N_NODES 100000
#define N_EDGES 1600000
#define D 128
#define N_PAD 102400   // 1024*100, padded so the scan needs no guards

// Scratch (no cudaMalloc allowed)
__device__ __half2 g_h[(size_t)N_NODES * (D / 2)];  // dis-premultiplied feats, fp16
__device__ int   g_deg[N_NODES];
__device__ float g_dis[N_NODES];
__device__ int   g_cnt[N_PAD];
__device__ int   g_off[N_PAD + 4];
__device__ int   g_cursor[N_PAD];
__device__ int   g_bucket[N_EDGES];

// ---------------- zero counters ----------------
__global__ __launch_bounds__(256) void zero_kernel()
{
    int i = blockIdx.x * 256 + threadIdx.x;
    if (i < N_PAD) g_cnt[i] = 0;
    if (i < N_NODES) g_deg[i] = 0;
}

// ---------------- fused histogram: deg over src, cnt over dst --------------
__global__ __launch_bounds__(256) void hist_kernel(const int* __restrict__ ei)
{
    int e = blockIdx.x * 256 + threadIdx.x;
    if (e < N_EDGES) {
        atomicAdd(&g_deg[ei[e]], 1);
        atomicAdd(&g_cnt[ei[N_EDGES + e]], 1);
    }
}

// ---------------- dis = rsqrt(deg + 1 self loop) ----------------
__global__ __launch_bounds__(256) void dis_kernel()
{
    int i = blockIdx.x * 256 + threadIdx.x;
    if (i < N_NODES) {
        g_dis[i] = rsqrtf((float)(g_deg[i] + 1));
    }
}

// ---------------- tf32 helpers ----------------
__device__ __forceinline__ unsigned f2tf32(float f) {
    unsigned u;
    asm("cvt.rna.tf32.f32 %0, %1;" : "=r"(u) : "f"(f));
    return u;
}
__device__ __forceinline__ void mma_tf32(
    float& d0, float& d1, float& d2, float& d3,
    unsigned a0, unsigned a1, unsigned a2, unsigned a3,
    unsigned b0, unsigned b1)
{
    asm volatile(
        "mma.sync.aligned.m16n8k8.row.col.f32.tf32.tf32.f32 "
        "{%0,%1,%2,%3}, {%4,%5,%6,%7}, {%8,%9}, {%0,%1,%2,%3};"
        : "+f"(d0), "+f"(d1), "+f"(d2), "+f"(d3)
        : "r"(a0), "r"(a1), "r"(a2), "r"(a3), "r"(b0), "r"(b1));
}

// ---------------- GEMM via tf32 tensor cores --------------------------------
// h' = fp16( dis ⊙ (x @ W^T + b) ).  Block tile 128x128, 8 warps, each warp
// 16 rows x 128 cols (16 n-tiles of m16n8k8).  x, W staged per 64-k chunk in
// dynamic smem as tf32 with stride-68 rows (bank-conflict-free fragments).
#define KC 64
#define XS(r, k) smem_u[(r) * 68 + (k)]
#define WS(n, k) smem_u[128 * 68 + (n) * 68 + (k)]

__global__ __launch_bounds__(256, 2) void gemm_mma_kernel(
    const float* __restrict__ x, const float* __restrict__ W,
    const float* __restrict__ b)
{
    extern __shared__ unsigned smem_u[];   // 2 * 128 * 68 * 4 = 69632 B

    const int tid  = threadIdx.x;
    const int lane = tid & 31;
    const int warp = tid >> 5;            // 0..7
    const int r    = lane >> 2;           // groupID 0..7
    const int c    = lane & 3;            // threadID-in-group 0..3
    const int lrow = warp * 16;           // warp's local row base
    const int m0   = blockIdx.x * 128;

    float acc[16][4];
#pragma unroll
    for (int t = 0; t < 16; t++)
#pragma unroll
        for (int j = 0; j < 4; j++) acc[t][j] = 0.f;

#pragma unroll
    for (int chunk = 0; chunk < 2; chunk++) {
        const int kc = chunk * KC;
        // stage x[128 rows][64 k] and W[128 n][64 k] as tf32
#pragma unroll
        for (int i = 0; i < 8; i++) {
            int f = tid + i * 256;         // 0..2047
            int row = f >> 4;              // 0..127
            int kq  = f & 15;              // float4 index, k = kq*4
            int grow = m0 + row;
            if (grow >= N_NODES) grow = N_NODES - 1;
            float4 xv = *reinterpret_cast<const float4*>(&x[(size_t)grow * D + kc + kq * 4]);
            uint4 xu = make_uint4(f2tf32(xv.x), f2tf32(xv.y), f2tf32(xv.z), f2tf32(xv.w));
            *reinterpret_cast<uint4*>(&XS(row, kq * 4)) = xu;
            float4 wv = *reinterpret_cast<const float4*>(&W[(size_t)row * D + kc + kq * 4]);
            uint4 wu = make_uint4(f2tf32(wv.x), f2tf32(wv.y), f2tf32(wv.z), f2tf32(wv.w));
            *reinterpret_cast<uint4*>(&WS(row, kq * 4)) = wu;
        }
        __syncthreads();

#pragma unroll
        for (int s = 0; s < 8; s++) {      // k-step of 8 within chunk
            unsigned a0 = XS(lrow + r,     s * 8 + c);
            unsigned a1 = XS(lrow + r + 8, s * 8 + c);
            unsigned a2 = XS(lrow + r,     s * 8 + c + 4);
            unsigned a3 = XS(lrow + r + 8, s * 8 + c + 4);
#pragma unroll
            for (int t = 0; t < 16; t++) { // n-tile (cols 8t..8t+7)
                unsigned b0 = WS(t * 8 + r, s * 8 + c);
                unsigned b1 = WS(t * 8 + r, s * 8 + c + 4);
                mma_tf32(acc[t][0], acc[t][1], acc[t][2], acc[t][3],
                         a0, a1, a2, a3, b0, b1);
            }
        }
        __syncthreads();
    }

    // epilogue: h'[row][col] = half( dis[row] * (acc + bias[col]) )
    const int row_a = m0 + lrow + r;
    const int row_b = row_a + 8;
    const float dda = (row_a < N_NODES) ? g_dis[row_a] : 0.f;
    const float ddb = (row_b < N_NODES) ? g_dis[row_b] : 0.f;
#pragma unroll
    for (int t = 0; t < 16; t++) {
        int col0 = t * 8 + c * 2;
        float2 bias = *reinterpret_cast<const float2*>(&b[col0]);
        if (row_a < N_NODES) {
            g_h[(size_t)row_a * 64 + t * 4 + c] =
                __floats2half2_rn(dda * (acc[t][0] + bias.x),
                                  dda * (acc[t][1] + bias.y));
        }
        if (row_b < N_NODES) {
            g_h[(size_t)row_b * 64 + t * 4 + c] =
                __floats2half2_rn(ddb * (acc[t][2] + bias.x),
                                  ddb * (acc[t][3] + bias.y));
        }
    }
}

// ---------------- single-block exclusive scan over g_cnt -------------------
__global__ __launch_bounds__(1024) void scan_kernel()
{
    __shared__ int ssum[1024];
    const int tid = threadIdx.x;
    const int4* cnt4 = reinterpret_cast<const int4*>(g_cnt);

    int s = 0;
#pragma unroll
    for (int k = 0; k < 25; k++) {
        int4 v = cnt4[tid * 25 + k];
        s += v.x + v.y + v.z + v.w;
    }
    ssum[tid] = s;
    __syncthreads();

    for (int d = 1; d < 1024; d <<= 1) {
        int v = (tid >= d) ? ssum[tid - d] : 0;
        __syncthreads();
        ssum[tid] += v;
        __syncthreads();
    }
    int running = (tid == 0) ? 0 : ssum[tid - 1];

    int4* off4 = reinterpret_cast<int4*>(g_off);
    int4* cur4 = reinterpret_cast<int4*>(g_cursor);
#pragma unroll
    for (int k = 0; k < 25; k++) {
        int4 cc = cnt4[tid * 25 + k];
        int4 o;
        o.x = running;              running += cc.x;
        o.y = running;              running += cc.y;
        o.z = running;              running += cc.z;
        o.w = running;              running += cc.w;
        off4[tid * 25 + k] = o;
        cur4[tid * 25 + k] = o;
    }
}

// ---------------- bucket fill: group src ids by dst -------------------------
__global__ __launch_bounds__(256) void fill_kernel(const int* __restrict__ ei)
{
    int e = blockIdx.x * 256 + threadIdx.x;
    if (e < N_EDGES) {
        int src = ei[e];
        int dst = ei[N_EDGES + e];
        int pos = atomicAdd(&g_cursor[dst], 1);
        g_bucket[pos] = src;
    }
}

// ---------------- gather: warp per node, shfl-distributed indices -----------
__global__ __launch_bounds__(256) void gather_kernel(float* __restrict__ out)
{
    const int node = blockIdx.x * 8 + (threadIdx.x >> 5);
    if (node >= N_NODES) return;
    const int lane = threadIdx.x & 31;
    const int hf   = lane >> 4;      // 0/1 half-warp
    const int sub  = lane & 15;      // 16 lanes cover a 256B fp16 row
    const unsigned FULL = 0xffffffffu;

    const int start = g_off[node];
    const int end   = g_off[node + 1];
    const int cnt   = end - start;
    const float dd  = g_dis[node];
    const uint4* hbase = reinterpret_cast<const uint4*>(g_h);

    int idx = (lane < cnt) ? g_bucket[start + lane] : 0;

    float2 a0 = make_float2(0.f, 0.f), a1 = a0, a2 = a0, a3 = a0;

    if (hf == 0) {
        uint4 u = hbase[(size_t)node * 16 + sub];
        a0 = __half22float2(*reinterpret_cast<__half2*>(&u.x));
        a1 = __half22float2(*reinterpret_cast<__half2*>(&u.y));
        a2 = __half22float2(*reinterpret_cast<__half2*>(&u.z));
        a3 = __half22float2(*reinterpret_cast<__half2*>(&u.w));
    }

    const int m = cnt < 32 ? cnt : 32;
    const int full8 = m & ~7;

    for (int base = 0; base < full8; base += 8) {
        int s0 = __shfl_sync(FULL, idx, base + hf);
        int s1 = __shfl_sync(FULL, idx, base + hf + 2);
        int s2 = __shfl_sync(FULL, idx, base + hf + 4);
        int s3 = __shfl_sync(FULL, idx, base + hf + 6);
        uint4 u0 = hbase[(size_t)s0 * 16 + sub];
        uint4 u1 = hbase[(size_t)s1 * 16 + sub];
        uint4 u2 = hbase[(size_t)s2 * 16 + sub];
        uint4 u3 = hbase[(size_t)s3 * 16 + sub];
        float2 f;
        f = __half22float2(*reinterpret_cast<__half2*>(&u0.x)); a0.x += f.x; a0.y += f.y;
        f = __half22float2(*reinterpret_cast<__half2*>(&u0.y)); a1.x += f.x; a1.y += f.y;
        f = __half22float2(*reinterpret_cast<__half2*>(&u0.z)); a2.x += f.x; a2.y += f.y;
        f = __half22float2(*reinterpret_cast<__half2*>(&u0.w)); a3.x += f.x; a3.y += f.y;
        f = __half22float2(*reinterpret_cast<__half2*>(&u1.x)); a0.x += f.x; a0.y += f.y;
        f = __half22float2(*reinterpret_cast<__half2*>(&u1.y)); a1.x += f.x; a1.y += f.y;
        f = __half22float2(*reinterpret_cast<__half2*>(&u1.z)); a2.x += f.x; a2.y += f.y;
        f = __half22float2(*reinterpret_cast<__half2*>(&u1.w)); a3.x += f.x; a3.y += f.y;
        f = __half22float2(*reinterpret_cast<__half2*>(&u2.x)); a0.x += f.x; a0.y += f.y;
        f = __half22float2(*reinterpret_cast<__half2*>(&u2.y)); a1.x += f.x; a1.y += f.y;
        f = __half22float2(*reinterpret_cast<__half2*>(&u2.z)); a2.x += f.x; a2.y += f.y;
        f = __half22float2(*reinterpret_cast<__half2*>(&u2.w)); a3.x += f.x; a3.y += f.y;
        f = __half22float2(*reinterpret_cast<__half2*>(&u3.x)); a0.x += f.x; a0.y += f.y;
        f = __half22float2(*reinterpret_cast<__half2*>(&u3.y)); a1.x += f.x; a1.y += f.y;
        f = __half22float2(*reinterpret_cast<__half2*>(&u3.z)); a2.x += f.x; a2.y += f.y;
        f = __half22float2(*reinterpret_cast<__half2*>(&u3.w)); a3.x += f.x; a3.y += f.y;
    }
    for (int rr = full8; rr < m; rr += 2) {
        int ee = rr + hf;
        int s0 = __shfl_sync(FULL, idx, ee & 31);
        if (ee < m) {
            uint4 u0 = hbase[(size_t)s0 * 16 + sub];
            float2 f;
            f = __half22float2(*reinterpret_cast<__half2*>(&u0.x)); a0.x += f.x; a0.y += f.y;
            f = __half22float2(*reinterpret_cast<__half2*>(&u0.y)); a1.x += f.x; a1.y += f.y;
            f = __half22float2(*reinterpret_cast<__half2*>(&u0.z)); a2.x += f.x; a2.y += f.y;
            f = __half22float2(*reinterpret_cast<__half2*>(&u0.w)); a3.x += f.x; a3.y += f.y;
        }
    }
    for (int j = start + 32 + hf; j < end; j += 2) {
        int s0 = g_bucket[j];
        uint4 u0 = hbase[(size_t)s0 * 16 + sub];
        float2 f;
        f = __half22float2(*reinterpret_cast<__half2*>(&u0.x)); a0.x += f.x; a0.y += f.y;
        f = __half22float2(*reinterpret_cast<__half2*>(&u0.y)); a1.x += f.x; a1.y += f.y;
        f = __half22float2(*reinterpret_cast<__half2*>(&u0.z)); a2.x += f.x; a2.y += f.y;
        f = __half22float2(*reinterpret_cast<__half2*>(&u0.w)); a3.x += f.x; a3.y += f.y;
    }

    a0.x += __shfl_xor_sync(FULL, a0.x, 16);
    a0.y += __shfl_xor_sync(FULL, a0.y, 16);
    a1.x += __shfl_xor_sync(FULL, a1.x, 16);
    a1.y += __shfl_xor_sync(FULL, a1.y, 16);
    a2.x += __shfl_xor_sync(FULL, a2.x, 16);
    a2.y += __shfl_xor_sync(FULL, a2.y, 16);
    a3.x += __shfl_xor_sync(FULL, a3.x, 16);
    a3.y += __shfl_xor_sync(FULL, a3.y, 16);

    const float coef = 0.125f;  // sqrt(2/128)
    float4 v;
    if (hf == 0) {
        v.x = a0.x; v.y = a0.y; v.z = a1.x; v.w = a1.y;
    } else {
        v.x = a2.x; v.y = a2.y; v.z = a3.x; v.w = a3.y;
    }
    v.x = coef * fmaxf(dd * v.x, 0.f);
    v.y = coef * fmaxf(dd * v.y, 0.f);
    v.z = coef * fmaxf(dd * v.z, 0.f);
    v.w = coef * fmaxf(dd * v.w, 0.f);
    *reinterpret_cast<float4*>(&out[(size_t)node * D + sub * 8 + hf * 4]) = v;
}

extern "C" void kernel_launch(void* const* d_in, const int* in_sizes, int n_in,
                              void* d_out, int out_size)
{
    const float* x  = (const float*)d_in[0];
    const int*   ei = (const int*)d_in[1];   // int32: JAX x64 disabled
    const float* W  = (const float*)d_in[2];
    const float* b  = (const float*)d_in[3];
    float* out = (float*)d_out;

    const int GEMM_SMEM = 2 * 128 * 68 * 4;  // 69632 B
    static bool attr_set = false;
    if (!attr_set) {
        cudaFuncSetAttribute(gemm_mma_kernel,
                             cudaFuncAttributeMaxDynamicSharedMemorySize, GEMM_SMEM);
        attr_set = true;
    }

    zero_kernel<<<(N_PAD + 255) / 256, 256>>>();
    hist_kernel<<<(N_EDGES + 255) / 256, 256>>>(ei);
    dis_kernel<<<(N_NODES + 255) / 256, 256>>>();
    gemm_mma_kernel<<<(N_NODES + 127) / 128, 256, GEMM_SMEM>>>(x, W, b);
    scan_kernel<<<1, 1024>>>();
    fill_kernel<<<(N_EDGES + 255) / 256, 256>>>(ei);
    gather_kernel<<<(N_NODES + 7) / 8, 256>>>(out);
}